// round 13
// baseline (speedup 1.0000x reference)
#include <cuda_runtime.h>
#include <cstdint>

// GRU over T2=256; 4096 independent rows.
// Kernel 1 (precompute): pre[t][o][row] = x_t @ Wx + bias for all t in 1..255
//   (the x-half of all three gate GEMMs; fully parallel, fma-bound).
// Kernel 2 (sequential): 255-step recurrence with K=64 (h-part only), acc
//   initialized from prefetched pre[]. fp32 via packed fma.rn.f32x2.

#define T2V 256
#define DV  64
#define NCTA 128
#define NT  256
#define GSL 32
#define NPRE_T 255
#define PRE_STEP 6144            // 192 cols * 32 rows per (cta, t)

// 255 * 4096 * 192 floats = 802 MB scratch (sanctioned __device__ global)
__device__ float g_pre[(size_t)NPRE_T * 4096 * 192];

typedef unsigned long long ull;

__device__ __forceinline__ ull pk2(float lo, float hi) {
    ull r;
    asm("mov.b64 %0, {%1, %2};" : "=l"(r) : "f"(lo), "f"(hi));
    return r;
}
__device__ __forceinline__ float2 upk2(ull v) {
    float2 f;
    asm("mov.b64 {%0, %1}, %2;" : "=f"(f.x), "=f"(f.y) : "l"(v));
    return f;
}
__device__ __forceinline__ void ffma2(ull& d, ull a, ull b) {
    asm("fma.rn.f32x2 %0, %1, %2, %0;" : "+l"(d) : "l"(a), "l"(b));
}
__device__ __forceinline__ ull dl(double d) { return __double_as_longlong(d); }

__device__ __forceinline__ float fsig(float x) {
    float e;
    asm("ex2.approx.f32 %0, %1;" : "=f"(e) : "f"(x * -1.4426950408889634f));
    float r;
    asm("rcp.approx.f32 %0, %1;" : "=f"(r) : "f"(1.0f + e));
    return r;
}
__device__ __forceinline__ float ftanh_(float x) {
    return fmaf(2.0f, fsig(2.0f * x), -1.0f);
}

// ===========================================================================
// Kernel 1: precompute pre-acts of the x-half.
// o layout: o<64 -> r-gate, 64..127 -> z-gate, 128..191 -> h-gate.
// pre[(cta)][(t-1)][o][row32], biases folded in.
// ===========================================================================
#define PX_WX 0                    // 64*192
#define PX_SX (64*192)             // 64*132 x^T slab [k][tt*32+row]
#define PX_FLOATS (PX_WX + 64*192 + 64*132)
#define PX_BYTES (PX_FLOATS * 4)
#define SXSTR 132

__global__ void __launch_bounds__(NT, 1)
gru4d_pre_kernel(const float* __restrict__ x,
                 const float* __restrict__ kh,
                 const float* __restrict__ kr,
                 const float* __restrict__ kz,
                 const float* __restrict__ bh,
                 const float* __restrict__ br,
                 const float* __restrict__ bz) {
    extern __shared__ float sm[];
    float* sWx = sm + PX_WX;
    float* sx  = sm + PX_SX;

    const int tid  = threadIdx.x;
    const int w    = tid >> 5;
    const int lane = tid & 31;
    const int rg4  = (lane >> 2) * 4;     // rows rg4..rg4+3
    const int cg   = lane & 3;
    const int ob   = 24 * w + 6 * cg;     // 6 output cols ob..ob+5
    const int row0 = blockIdx.x * 32;
    const size_t rstr = (size_t)T2V * DV;
    const size_t base = (size_t)blockIdx.x * NPRE_T * PRE_STEP;

    // stage weights (x-half rows k=0..63 of each kernel)
    for (int idx = tid; idx < 64 * 192; idx += NT) {
        int k = idx / 192, o = idx % 192;
        float v;
        if (o < 64)       v = kr[k * 64 + o];
        else if (o < 128) v = kz[k * 64 + (o - 64)];
        else              v = kh[k * 64 + (o - 128)];
        sWx[idx] = v;
    }
    // biases for this thread's 6 cols
    float bb[6];
    #pragma unroll
    for (int j = 0; j < 6; j++) {
        int o = ob + j;
        bb[j] = (o < 64) ? br[o] : (o < 128) ? bz[o - 64] : bh[o - 128];
    }

    for (int p = 0; p < 64; ++p) {
        int t0 = 1 + 4 * p;
        __syncthreads();   // previous pass done reading sx
        // stage x^T slab for t in [t0, t0+3]
        #pragma unroll
        for (int i = 0; i < 8; i++) {
            int u = tid + 256 * i;          // 0..2047
            int kq   = u & 15;
            int r    = (u >> 4) & 31;
            int tseg = u >> 9;
            int t = t0 + tseg;
            if (t <= 255) {
                float4 v = *(const float4*)&x[(size_t)(row0 + r) * rstr
                                              + (size_t)t * DV + 4 * kq];
                sx[(4 * kq + 0) * SXSTR + tseg * 32 + r] = v.x;
                sx[(4 * kq + 1) * SXSTR + tseg * 32 + r] = v.y;
                sx[(4 * kq + 2) * SXSTR + tseg * 32 + r] = v.z;
                sx[(4 * kq + 3) * SXSTR + tseg * 32 + r] = v.w;
            }
        }
        __syncthreads();

        // acc[rowpair][tt][j]
        ull acc[2][4][6];
        #pragma unroll
        for (int tt = 0; tt < 4; tt++)
            #pragma unroll
            for (int j = 0; j < 6; j++) {
                acc[0][tt][j] = pk2(bb[j], bb[j]);
                acc[1][tt][j] = pk2(bb[j], bb[j]);
            }

        for (int k = 0; k < 64; ++k) {
            ull wb[6];
            #pragma unroll
            for (int jj = 0; jj < 3; jj++) {
                float2 wv = *(const float2*)&sWx[k * 192 + ob + 2 * jj];
                wb[2 * jj]     = pk2(wv.x, wv.x);
                wb[2 * jj + 1] = pk2(wv.y, wv.y);
            }
            #pragma unroll
            for (int tt = 0; tt < 4; tt++) {
                double2 gd = *(const double2*)&sx[k * SXSTR + tt * 32 + rg4];
                ull ga = dl(gd.x), gb = dl(gd.y);
                #pragma unroll
                for (int j = 0; j < 6; j++) {
                    ffma2(acc[0][tt][j], ga, wb[j]);
                    ffma2(acc[1][tt][j], gb, wb[j]);
                }
            }
        }

        // store
        #pragma unroll
        for (int tt = 0; tt < 4; tt++) {
            int t = t0 + tt;
            if (t <= 255) {
                float* pp = g_pre + base + (size_t)(t - 1) * PRE_STEP;
                #pragma unroll
                for (int j = 0; j < 6; j++) {
                    float2 lo = upk2(acc[0][tt][j]);
                    float2 hi = upk2(acc[1][tt][j]);
                    *(float4*)&pp[(ob + j) * 32 + rg4] =
                        make_float4(lo.x, lo.y, hi.x, hi.y);
                }
            }
        }
    }
}

// ===========================================================================
// Kernel 2: sequential recurrence, K=64 (h-part only).
// ===========================================================================
#define SQ_W1  0                         // 64*128 : rows 64..127 of (Wr|Wz)
#define SQ_WH2 (64*128)                  // 64*64  : rows 64..127 of Wh
#define SQ_HB  (SQ_W1 + 64*128 + 64*64)  // 64*GSL : h[c][row] (also g for phase1)
#define SQ_GHR (SQ_HB + 64*GSL)          // 64*GSL : (h*r)[c][row]
#define SQ_ZB  (SQ_GHR + 64*GSL)         // 64*GSL : z[c][row]
#define SQ_FLOATS (SQ_ZB + 64*GSL)
#define SQ_BYTES (SQ_FLOATS * 4)

__global__ void __launch_bounds__(NT, 1)
gru4d_seq_kernel(const float* __restrict__ x,
                 const float* __restrict__ kh,
                 const float* __restrict__ kr,
                 const float* __restrict__ kz,
                 float* __restrict__ out) {
    extern __shared__ float sm[];
    float* sW1  = sm + SQ_W1;
    float* sWh2 = sm + SQ_WH2;
    float* shb  = sm + SQ_HB;
    float* sghr = sm + SQ_GHR;
    float* szb  = sm + SQ_ZB;

    const int tid  = threadIdx.x;
    const int w    = tid >> 5;
    const int lane = tid & 31;
    const int rg4  = (lane >> 2) * 4;
    const int cg   = lane & 3;
    const int obase  = 16 * w + 4 * cg;   // phase-1 cols (of 128)
    const int c2base = 8 * w + 2 * cg;    // phase-2 cols (of 64)
    const int row0 = blockIdx.x * 32;
    const size_t rstr = (size_t)T2V * DV;
    const size_t base = (size_t)blockIdx.x * NPRE_T * PRE_STEP;

    // stage h-half weights (rows 64..127)
    for (int idx = tid; idx < 64 * 128; idx += NT) {
        int k = idx >> 7, o = idx & 127;
        sW1[idx] = (o < 64) ? kr[(64 + k) * 64 + o] : kz[(64 + k) * 64 + (o - 64)];
    }
    for (int idx = tid; idx < 64 * 64; idx += NT) {
        int k = idx >> 6, o = idx & 63;
        sWh2[idx] = kh[(64 + k) * 64 + o];
    }

    // init h0 = x[:,:,0,:]
    #pragma unroll
    for (int j = 0; j < 2; j++) {
        int c = c2base + j;
        #pragma unroll
        for (int i = 0; i < 4; i++)
            shb[c * GSL + rg4 + i] = x[(size_t)(row0 + rg4 + i) * rstr + c];
    }
    __syncthreads();

    // preload pre-acts for t=1
    float4 pv1[4], pv2[2];
    {
        const float* pp = g_pre + base;   // t=1
        #pragma unroll
        for (int j = 0; j < 4; j++)
            pv1[j] = *(const float4*)&pp[(obase + j) * 32 + rg4];
        #pragma unroll
        for (int j = 0; j < 2; j++)
            pv2[j] = *(const float4*)&pp[(128 + c2base + j) * 32 + rg4];
    }

    for (int t = 1; t < T2V; ++t) {
        // prefetch pre-acts for t+1 (hidden under phase-1)
        float4 pn1[4], pn2[2];
        if (t < T2V - 1) {
            const float* pp = g_pre + base + (size_t)t * PRE_STEP;  // t+1
            #pragma unroll
            for (int j = 0; j < 4; j++)
                pn1[j] = *(const float4*)&pp[(obase + j) * 32 + rg4];
            #pragma unroll
            for (int j = 0; j < 2; j++)
                pn2[j] = *(const float4*)&pp[(128 + c2base + j) * 32 + rg4];
        }

        // ===== phase 1: r|z += h @ W1  (K = 64) =====
        ull acc[4][2];
        #pragma unroll
        for (int j = 0; j < 4; j++) {
            acc[j][0] = pk2(pv1[j].x, pv1[j].y);
            acc[j][1] = pk2(pv1[j].z, pv1[j].w);
        }
        #pragma unroll 8
        for (int k = 0; k < 64; k++) {
            float4 wv = *(const float4*)&sW1[k * 128 + obase];
            double2 gd = *(const double2*)&shb[k * GSL + rg4];
            ull ga = dl(gd.x), gb = dl(gd.y);
            ull W0 = pk2(wv.x, wv.x), W1 = pk2(wv.y, wv.y);
            ull W2 = pk2(wv.z, wv.z), W3 = pk2(wv.w, wv.w);
            ffma2(acc[0][0], ga, W0); ffma2(acc[0][1], gb, W0);
            ffma2(acc[1][0], ga, W1); ffma2(acc[1][1], gb, W1);
            ffma2(acc[2][0], ga, W2); ffma2(acc[2][1], gb, W2);
            ffma2(acc[3][0], ga, W3); ffma2(acc[3][1], gb, W3);
        }

        // epilogue 1
        if (w < 4) {
            #pragma unroll
            for (int j = 0; j < 4; j++) {
                int c = obase + j;                  // r col
                float2 p0 = upk2(acc[j][0]);
                float2 p1 = upk2(acc[j][1]);
                float s0 = fsig(p0.x), s1 = fsig(p0.y);
                float s2 = fsig(p1.x), s3 = fsig(p1.y);
                float4 h4 = *(const float4*)&shb[c * GSL + rg4];
                *(float4*)&sghr[c * GSL + rg4] =
                    make_float4(h4.x * s0, h4.y * s1, h4.z * s2, h4.w * s3);
            }
        } else {
            #pragma unroll
            for (int j = 0; j < 4; j++) {
                int c = obase - 64 + j;             // z col
                float2 p0 = upk2(acc[j][0]);
                float2 p1 = upk2(acc[j][1]);
                *(float4*)&szb[c * GSL + rg4] =
                    make_float4(fsig(p0.x), fsig(p0.y), fsig(p1.x), fsig(p1.y));
            }
        }
        __syncthreads();   // (h*r, z) published; all phase-1 reads of shb done

        // ===== phase 2: hcand += (h*r) @ Wh2  (K = 64) =====
        ull a2[2][2];
        a2[0][0] = pk2(pv2[0].x, pv2[0].y); a2[0][1] = pk2(pv2[0].z, pv2[0].w);
        a2[1][0] = pk2(pv2[1].x, pv2[1].y); a2[1][1] = pk2(pv2[1].z, pv2[1].w);

        #pragma unroll 8
        for (int k = 0; k < 64; k++) {
            float2 wv = *(const float2*)&sWh2[k * 64 + c2base];
            double2 gd = *(const double2*)&sghr[k * GSL + rg4];
            ull ga = dl(gd.x), gb = dl(gd.y);
            ull W0 = pk2(wv.x, wv.x), W1 = pk2(wv.y, wv.y);
            ffma2(a2[0][0], ga, W0); ffma2(a2[0][1], gb, W0);
            ffma2(a2[1][0], ga, W1); ffma2(a2[1][1], gb, W1);
        }

        // epilogue 2: tanh + blend; publish h
        #pragma unroll
        for (int j = 0; j < 2; j++) {
            int c = c2base + j;
            float2 p0 = upk2(a2[j][0]);
            float2 p1 = upk2(a2[j][1]);
            float hc0 = ftanh_(p0.x), hc1 = ftanh_(p0.y);
            float hc2 = ftanh_(p1.x), hc3 = ftanh_(p1.y);
            float4 z4 = *(const float4*)&szb[c * GSL + rg4];
            float4 h4 = *(const float4*)&shb[c * GSL + rg4];
            *(float4*)&shb[c * GSL + rg4] =
                make_float4(fmaf(z4.x, hc0 - h4.x, h4.x),
                            fmaf(z4.y, hc1 - h4.y, h4.y),
                            fmaf(z4.z, hc2 - h4.z, h4.z),
                            fmaf(z4.w, hc3 - h4.w, h4.w));
        }
        pv1[0] = pn1[0]; pv1[1] = pn1[1]; pv1[2] = pn1[2]; pv1[3] = pn1[3];
        pv2[0] = pn2[0]; pv2[1] = pn2[1];
        __syncthreads();   // h published for next step
    }

    // write h_final
    #pragma unroll
    for (int j = 0; j < 2; j++) {
        int c = c2base + j;
        float4 h4 = *(const float4*)&shb[c * GSL + rg4];
        out[(size_t)(row0 + rg4 + 0) * DV + c] = h4.x;
        out[(size_t)(row0 + rg4 + 1) * DV + c] = h4.y;
        out[(size_t)(row0 + rg4 + 2) * DV + c] = h4.z;
        out[(size_t)(row0 + rg4 + 3) * DV + c] = h4.w;
    }
}

extern "C" void kernel_launch(void* const* d_in, const int* in_sizes, int n_in,
                              void* d_out, int out_size) {
    const float* x  = (const float*)d_in[0];
    const float* kh = (const float*)d_in[1];
    const float* kr = (const float*)d_in[2];
    const float* kz = (const float*)d_in[3];
    const float* bh = (const float*)d_in[4];
    const float* br = (const float*)d_in[5];
    const float* bz = (const float*)d_in[6];
    float* out = (float*)d_out;

    static bool attr_set = false;
    if (!attr_set) {
        cudaFuncSetAttribute(gru4d_pre_kernel,
                             cudaFuncAttributeMaxDynamicSharedMemorySize, PX_BYTES);
        cudaFuncSetAttribute(gru4d_seq_kernel,
                             cudaFuncAttributeMaxDynamicSharedMemorySize, SQ_BYTES);
        attr_set = true;
    }
    gru4d_pre_kernel<<<NCTA, NT, PX_BYTES>>>(x, kh, kr, kz, bh, br, bz);
    gru4d_seq_kernel<<<NCTA, NT, SQ_BYTES>>>(x, kh, kr, kz, out);
}